// round 13
// baseline (speedup 1.0000x reference)
#include <cuda_runtime.h>
#include <cuda_fp16.h>
#include <cstdint>

// Problem constants
#define B_   4
#define T_   2048
#define D_   2048
#define H_   16
#define HD_  128
#define DFF_ 8192
#define R_   (B_*T_)      // 8192 rows

// ------------------------------------------------------------------
// Device scratch
// ------------------------------------------------------------------
__device__ __align__(256) __half g_h  [(size_t)R_*D_];
__device__ __align__(256) __half g_h2 [(size_t)R_*D_];
__device__ __align__(256) __half g_Wq [(size_t)H_*D_*HD_];
__device__ __align__(256) __half g_Wk [(size_t)H_*D_*HD_];
__device__ __align__(256) __half g_Wv [(size_t)H_*D_*HD_];
__device__ __align__(256) __half g_W1 [(size_t)D_*DFF_];
__device__ __align__(256) __half g_W2 [(size_t)DFF_*D_];
__device__ __align__(256) __half g_q  [(size_t)B_*H_*T_*HD_];
__device__ __align__(256) __half g_k  [(size_t)B_*H_*T_*HD_];
__device__ __align__(256) __half g_v  [(size_t)B_*H_*T_*HD_];
__device__ __align__(256) __half g_att[(size_t)R_*D_];
__device__ __align__(256) __half g_ff [(size_t)R_*DFF_];

// ------------------------------------------------------------------
// Helpers
// ------------------------------------------------------------------
__device__ __forceinline__ uint32_t smem_u32(const void* p) {
    return (uint32_t)__cvta_generic_to_shared(p);
}
__device__ __forceinline__ void cp16(uint32_t dst, const void* src) {
    asm volatile("cp.async.cg.shared.global [%0], [%1], 16;" :: "r"(dst), "l"(src));
}
#define CP_COMMIT() asm volatile("cp.async.commit_group;")
#define CP_WAIT0()  asm volatile("cp.async.wait_group 0;")
#define CP_WAIT1()  asm volatile("cp.async.wait_group 1;")

__device__ __forceinline__ void ldsm_x4(uint32_t& r0, uint32_t& r1, uint32_t& r2, uint32_t& r3, uint32_t a) {
    asm volatile("ldmatrix.sync.aligned.m8n8.x4.shared.b16 {%0,%1,%2,%3}, [%4];"
                 : "=r"(r0), "=r"(r1), "=r"(r2), "=r"(r3) : "r"(a));
}
__device__ __forceinline__ void ldsm_x4_t(uint32_t& r0, uint32_t& r1, uint32_t& r2, uint32_t& r3, uint32_t a) {
    asm volatile("ldmatrix.sync.aligned.m8n8.x4.trans.shared.b16 {%0,%1,%2,%3}, [%4];"
                 : "=r"(r0), "=r"(r1), "=r"(r2), "=r"(r3) : "r"(a));
}
__device__ __forceinline__ void mma_16816(float* c, const uint32_t* a, uint32_t b0, uint32_t b1v) {
    asm volatile(
        "mma.sync.aligned.m16n8k16.row.col.f32.f16.f16.f32 "
        "{%0,%1,%2,%3}, {%4,%5,%6,%7}, {%8,%9}, {%0,%1,%2,%3};\n"
        : "+f"(c[0]), "+f"(c[1]), "+f"(c[2]), "+f"(c[3])
        : "r"(a[0]), "r"(a[1]), "r"(a[2]), "r"(a[3]), "r"(b0), "r"(b1v));
}
__device__ __forceinline__ uint32_t packh2(float a, float b) {
    __half2 h = __floats2half2_rn(a, b);
    return *reinterpret_cast<uint32_t*>(&h);
}

// ------------------------------------------------------------------
// fp32 -> fp16, 8 elems/thread, up to 3 concatenated ranges
// ------------------------------------------------------------------
__global__ void __launch_bounds__(256) f2h3_kernel(
    const float4* __restrict__ s0, uint4* __restrict__ d0, long n0,
    const float4* __restrict__ s1, uint4* __restrict__ d1, long n1,
    const float4* __restrict__ s2, uint4* __restrict__ d2)
{
    long i = (long)blockIdx.x * 256 + threadIdx.x;
    const float4* src; uint4* dst;
    if      (i < n0)       { src = s0; dst = d0; }
    else if (i < n0 + n1)  { src = s1; dst = d1; i -= n0; }
    else                   { src = s2; dst = d2; i -= n0 + n1; }
    float4 a = src[2*i], c = src[2*i + 1];
    __half2 h0 = __floats2half2_rn(a.x, a.y);
    __half2 h1 = __floats2half2_rn(a.z, a.w);
    __half2 h2 = __floats2half2_rn(c.x, c.y);
    __half2 h3 = __floats2half2_rn(c.z, c.w);
    uint4 o;
    o.x = *(uint32_t*)&h0; o.y = *(uint32_t*)&h1;
    o.z = *(uint32_t*)&h2; o.w = *(uint32_t*)&h3;
    dst[i] = o;
}

// ------------------------------------------------------------------
// LayerNorm (block per row of D_=2048, 256 threads) — vectorized 16B
// ------------------------------------------------------------------
__global__ void __launch_bounds__(256) ln_kernel(
    const float* __restrict__ x, const float* __restrict__ g,
    const float* __restrict__ b, __half* __restrict__ out)
{
    int r = blockIdx.x;
    size_t off = (size_t)r * D_;
    int c0 = threadIdx.x * 8;
    float4 xa = *(const float4*)(x + off + c0);
    float4 xb = *(const float4*)(x + off + c0 + 4);
    float v[8] = {xa.x, xa.y, xa.z, xa.w, xb.x, xb.y, xb.z, xb.w};
    float s = 0.f, s2 = 0.f;
#pragma unroll
    for (int j = 0; j < 8; j++) { s += v[j]; s2 += v[j]*v[j]; }
    __shared__ float red[32];
#pragma unroll
    for (int o = 16; o; o >>= 1) { s += __shfl_xor_sync(~0u, s, o); s2 += __shfl_xor_sync(~0u, s2, o); }
    int wid = threadIdx.x >> 5;
    if ((threadIdx.x & 31) == 0) { red[wid] = s; red[8 + wid] = s2; }
    __syncthreads();
    if (threadIdx.x < 32) {
        float a  = (threadIdx.x < 8) ? red[threadIdx.x]   : 0.f;
        float c2 = (threadIdx.x < 8) ? red[8+threadIdx.x] : 0.f;
#pragma unroll
        for (int o = 4; o; o >>= 1) { a += __shfl_xor_sync(~0u, a, o); c2 += __shfl_xor_sync(~0u, c2, o); }
        if (threadIdx.x == 0) { red[16] = a; red[17] = c2; }
    }
    __syncthreads();
    float mu  = red[16] * (1.f / D_);
    float var = red[17] * (1.f / D_) - mu * mu;
    float rs  = rsqrtf(var + 1e-5f);
    float4 ga = *(const float4*)(g + c0), gb = *(const float4*)(g + c0 + 4);
    float4 ba = *(const float4*)(b + c0), bb = *(const float4*)(b + c0 + 4);
    float gg[8]  = {ga.x, ga.y, ga.z, ga.w, gb.x, gb.y, gb.z, gb.w};
    float bbv[8] = {ba.x, ba.y, ba.z, ba.w, bb.x, bb.y, bb.z, bb.w};
    uint4 o4;
    uint32_t* op = (uint32_t*)&o4;
#pragma unroll
    for (int j = 0; j < 4; j++) {
        op[j] = packh2((v[2*j]   - mu) * rs * gg[2*j]   + bbv[2*j],
                       (v[2*j+1] - mu) * rs * gg[2*j+1] + bbv[2*j+1]);
    }
    *(uint4*)(out + off + c0) = o4;
}

// Fused: x1 = x + att ; write x1 (fp32) ; h2 = LN(x1) — vectorized 16B
__global__ void __launch_bounds__(256) resid_ln_kernel(
    const float* __restrict__ x, const float* __restrict__ g,
    const float* __restrict__ b, float* __restrict__ xout,
    __half* __restrict__ h2)
{
    int r = blockIdx.x;
    size_t off = (size_t)r * D_;
    int c0 = threadIdx.x * 8;
    float4 xa = *(const float4*)(x + off + c0);
    float4 xb = *(const float4*)(x + off + c0 + 4);
    uint4 at = *(const uint4*)(g_att + off + c0);
    const __half2* ah = (const __half2*)&at;
    float v[8];
    {
        float2 a0 = __half22float2(ah[0]), a1 = __half22float2(ah[1]);
        float2 a2 = __half22float2(ah[2]), a3 = __half22float2(ah[3]);
        v[0] = xa.x + a0.x; v[1] = xa.y + a0.y;
        v[2] = xa.z + a1.x; v[3] = xa.w + a1.y;
        v[4] = xb.x + a2.x; v[5] = xb.y + a2.y;
        v[6] = xb.z + a3.x; v[7] = xb.w + a3.y;
    }
    *(float4*)(xout + off + c0)     = make_float4(v[0], v[1], v[2], v[3]);
    *(float4*)(xout + off + c0 + 4) = make_float4(v[4], v[5], v[6], v[7]);
    float s = 0.f, s2 = 0.f;
#pragma unroll
    for (int j = 0; j < 8; j++) { s += v[j]; s2 += v[j]*v[j]; }
    __shared__ float red[32];
#pragma unroll
    for (int o = 16; o; o >>= 1) { s += __shfl_xor_sync(~0u, s, o); s2 += __shfl_xor_sync(~0u, s2, o); }
    int wid = threadIdx.x >> 5;
    if ((threadIdx.x & 31) == 0) { red[wid] = s; red[8 + wid] = s2; }
    __syncthreads();
    if (threadIdx.x < 32) {
        float a  = (threadIdx.x < 8) ? red[threadIdx.x]   : 0.f;
        float c2 = (threadIdx.x < 8) ? red[8+threadIdx.x] : 0.f;
#pragma unroll
        for (int o = 4; o; o >>= 1) { a += __shfl_xor_sync(~0u, a, o); c2 += __shfl_xor_sync(~0u, c2, o); }
        if (threadIdx.x == 0) { red[16] = a; red[17] = c2; }
    }
    __syncthreads();
    float mu  = red[16] * (1.f / D_);
    float var = red[17] * (1.f / D_) - mu * mu;
    float rs  = rsqrtf(var + 1e-5f);
    float4 ga = *(const float4*)(g + c0), gb = *(const float4*)(g + c0 + 4);
    float4 ba = *(const float4*)(b + c0), bb = *(const float4*)(b + c0 + 4);
    float gg[8]  = {ga.x, ga.y, ga.z, ga.w, gb.x, gb.y, gb.z, gb.w};
    float bbv[8] = {ba.x, ba.y, ba.z, ba.w, bb.x, bb.y, bb.z, bb.w};
    uint4 o4;
    uint32_t* op = (uint32_t*)&o4;
#pragma unroll
    for (int j = 0; j < 4; j++) {
        op[j] = packh2((v[2*j]   - mu) * rs * gg[2*j]   + bbv[2*j],
                       (v[2*j+1] - mu) * rs * gg[2*j+1] + bbv[2*j+1]);
    }
    *(uint4*)(h2 + off + c0) = o4;
}

// ------------------------------------------------------------------
// GEMM: C[M,N] = A[M,K]*B[K,N], 3-stage cp.async, ldmatrix, swizzled.
// BM=128, BN=128, BK=64; 256 threads (2x4 warps), warp tile 64x32.
// 2 CTAs/SM, one __syncthreads per k-tile.
//   mode 0: QKV for head group grp (blockIdx.x: 0..11 => which*4 + headofs)
//   mode 1: FFN1 (relu)   mode 2: FFN2 (xout += C + b2)
// ------------------------------------------------------------------
#define BM 128
#define BN 128
#define BK 64
#define ASTG (BM*BK*2)            // 16384 B
#define BSTG (BK*BN*2)            // 16384 B
#define STG  (ASTG + BSTG)        // 32768 B
#define GSMEM (3*STG)             // 98304 B

__global__ void __launch_bounds__(256, 2) gemm_kernel(
    int mode, int grp,
    const float* __restrict__ bq, const float* __restrict__ bk, const float* __restrict__ bv,
    const float* __restrict__ b1, const float* __restrict__ b2,
    float* __restrict__ xout)
{
    const __half* A; int K;
    if (mode == 0)      { A = g_h;  K = D_;   }
    else if (mode == 1) { A = g_h2; K = D_;   }
    else                { A = g_ff; K = DFF_; }

    // mode 0: decode (which, head) from tile index + group
    int which = 0, head = 0;
    const __half* W0 = nullptr;
    if (mode == 0) {
        int tile = blockIdx.x;              // 0..11
        which = tile >> 2;                  // 0..2
        head  = grp * 4 + (tile & 3);       // global head
        W0 = ((which == 0) ? g_Wq : (which == 1) ? g_Wk : g_Wv) + (size_t)head * (D_ * HD_);
    }

    const int m0 = blockIdx.y * BM;
    const int n0 = blockIdx.x * BN;         // used by modes 1,2
    const int nkt = K / BK;

    extern __shared__ __half dsm[];
    const uint32_t sbase = smem_u32(dsm);

    const int tid  = threadIdx.x;
    const int wid  = tid >> 5;
    const int lane = tid & 31;
    const int wm   = wid & 1;
    const int wn   = wid >> 1;

    float acc[4][4][4];
#pragma unroll
    for (int i = 0; i < 4; i++)
#pragma unroll
        for (int j = 0; j < 4; j++)
#pragma unroll
            for (int q = 0; q < 4; q++) acc[i][j][q] = 0.f;

    auto loadStage = [&](int kt, int s) {
        uint32_t sA = sbase + s * STG;
        uint32_t sB = sA + ASTG;
#pragma unroll
        for (int i = 0; i < 4; i++) {
            int idx = tid + i * 256;
            int r = idx >> 3, c = idx & 7;
            int sc = c ^ (r & 7);
            cp16(sA + r * 128 + sc * 16, A + (size_t)(m0 + r) * K + kt * BK + c * 8);
        }
#pragma unroll
        for (int i = 0; i < 4; i++) {
            int idx = tid + i * 256;
            int r = idx >> 4, c = idx & 15;
            int sc = ((c & 7) ^ (r & 7)) | (c & 8);
            const __half* src;
            if (mode == 0) {
                src = W0 + (size_t)(kt * BK + r) * HD_ + c * 8;
            } else if (mode == 1) {
                src = g_W1 + (size_t)(kt * BK + r) * DFF_ + n0 + c * 8;
            } else {
                src = g_W2 + (size_t)(kt * BK + r) * D_ + n0 + c * 8;
            }
            cp16(sB + r * 256 + sc * 16, src);
        }
    };

    loadStage(0, 0); CP_COMMIT();
    loadStage(1, 1); CP_COMMIT();

    for (int kt = 0; kt < nkt; kt++) {
        if (kt + 1 < nkt) { CP_WAIT1(); } else { CP_WAIT0(); }
        __syncthreads();
        if (kt + 2 < nkt) { loadStage(kt + 2, (kt + 2) % 3); CP_COMMIT(); }

        uint32_t sA = sbase + (kt % 3) * STG;
        uint32_t sB = sA + ASTG;

#pragma unroll
        for (int kk = 0; kk < 4; kk++) {
            uint32_t a[4][4];
#pragma unroll
            for (int mt = 0; mt < 4; mt++) {
                int row = wm * 64 + mt * 16 + (lane & 15);
                int ch  = 2 * kk + (lane >> 4);
                ldsm_x4(a[mt][0], a[mt][1], a[mt][2], a[mt][3],
                        sA + row * 128 + ((ch ^ (row & 7)) << 4));
            }
            uint32_t bf[4][2];
#pragma unroll
            for (int ntp = 0; ntp < 2; ntp++) {
                int row = kk * 16 + ((lane >> 3) & 1) * 8 + (lane & 7);
                int ch  = wn * 4 + ntp * 2 + (lane >> 4);
                int sc  = ((ch & 7) ^ (row & 7)) | (ch & 8);
                ldsm_x4_t(bf[2*ntp][0], bf[2*ntp][1], bf[2*ntp+1][0], bf[2*ntp+1][1],
                          sB + row * 256 + sc * 16);
            }
#pragma unroll
            for (int nt = 0; nt < 4; nt++)
#pragma unroll
                for (int mt = 0; mt < 4; mt++)
                    mma_16816(acc[mt][nt], a[mt], bf[nt][0], bf[nt][1]);
        }
    }

    // ---- Epilogue ----
    if (mode == 0) {
        const float* bias = ((which == 0) ? bq : (which == 1) ? bk : bv) + head * HD_;
        __half* qkv = (which == 0) ? g_q : (which == 1) ? g_k : g_v;
#pragma unroll
        for (int mt = 0; mt < 4; mt++) {
#pragma unroll
            for (int nt = 0; nt < 4; nt++) {
                float* cc = acc[mt][nt];
                int row0 = m0 + wm * 64 + mt * 16 + (lane >> 2);
                int e    = wn * 32 + nt * 8 + ((lane & 3) << 1);
                float bb0 = bias[e], bb1 = bias[e + 1];
#pragma unroll
                for (int rr = 0; rr < 2; rr++) {
                    int row = row0 + rr * 8;
                    int bb = row >> 11, t = row & (T_ - 1);
                    __half* dst = qkv + (((size_t)(bb * H_ + head) * T_ + t) * HD_) + e;
                    *(__half2*)dst = __floats2half2_rn(cc[rr*2] + bb0, cc[rr*2+1] + bb1);
                }
            }
        }
    } else if (mode == 1) {
#pragma unroll
        for (int mt = 0; mt < 4; mt++) {
#pragma unroll
            for (int nt = 0; nt < 4; nt++) {
                float* cc = acc[mt][nt];
                int row0 = m0 + wm * 64 + mt * 16 + (lane >> 2);
                int col  = n0 + wn * 32 + nt * 8 + ((lane & 3) << 1);
                float bb0 = b1[col], bb1 = b1[col + 1];
#pragma unroll
                for (int rr = 0; rr < 2; rr++) {
                    int row = row0 + rr * 8;
                    float v0 = fmaxf(cc[rr*2]   + bb0, 0.f);
                    float v1 = fmaxf(cc[rr*2+1] + bb1, 0.f);
                    *(__half2*)(g_ff + (size_t)row * DFF_ + col) = __floats2half2_rn(v0, v1);
                }
            }
        }
    } else {
#pragma unroll
        for (int mt = 0; mt < 4; mt++) {
#pragma unroll
            for (int nt = 0; nt < 4; nt++) {
                float* cc = acc[mt][nt];
                int row0 = m0 + wm * 64 + mt * 16 + (lane >> 2);
                int col  = n0 + wn * 32 + nt * 8 + ((lane & 3) << 1);
                float bb0 = b2[col], bb1 = b2[col + 1];
#pragma unroll
                for (int rr = 0; rr < 2; rr++) {
                    int row = row0 + rr * 8;
                    float2* d = (float2*)(xout + (size_t)row * D_ + col);
                    float2 val = *d;
                    val.x += cc[rr*2]   + bb0;
                    val.y += cc[rr*2+1] + bb1;
                    *d = val;
                }
            }
        }
    }
}

// ------------------------------------------------------------------
// Flash attention for one head group: grid (T/64, B_*4).
// 128 threads; double-buffered cp.async K/V; diagonal tile first.
// ------------------------------------------------------------------
#define AQ 64
#define AK 64
#define AKVSTG (AK*HD_*2)          // 16384 B per tensor per stage
#define ASMEM  (4*AKVSTG)          // 65536 B

__global__ void __launch_bounds__(128) attn_kernel(int grp) {
    const int b  = blockIdx.y >> 2;
    const int h  = grp * 4 + (blockIdx.y & 3);
    const int bh = b * H_ + h;
    const int t0 = blockIdx.x * AQ;

    const __half* qbase = g_q + (size_t)bh * T_ * HD_;
    const __half* kbase = g_k + (size_t)bh * T_ * HD_;
    const __half* vbase = g_v + (size_t)bh * T_ * HD_;

    extern __shared__ __half kvsm[];
    const uint32_t kvbase = smem_u32(kvsm);

    const int tid  = threadIdx.x;
    const int wid  = tid >> 5;
    const int lane = tid & 31;
    const int qr   = wid * 16 + (lane >> 2);

    uint32_t qa[8][4];
    {
        const __half* qp = qbase + (size_t)t0 * HD_;
#pragma unroll
        for (int kk = 0; kk < 8; kk++) {
            int c = ((lane & 3) << 1) + kk * 16;
            qa[kk][0] = *(const uint32_t*)(qp + (size_t)qr       * HD_ + c);
            qa[kk][1] = *(const uint32_t*)(qp + (size_t)(qr + 8) * HD_ + c);
            qa[kk][2] = *(const uint32_t*)(qp + (size_t)qr       * HD_ + c + 8);
            qa[kk][3] = *(const uint32_t*)(qp + (size_t)(qr + 8) * HD_ + c + 8);
        }
    }

    float m_run[2] = {-1e30f, -1e30f};
    float l_run[2] = {0.f, 0.f};
    float o[16][4];
#pragma unroll
    for (int i = 0; i < 16; i++)
#pragma unroll
        for (int q = 0; q < 4; q++) o[i][q] = 0.f;

    const float scale = 0.08838834764831845f;
    const int jmax = t0 / AK;

    auto ord = [&](int i) { return (i == 0) ? jmax : (i - 1); };

    auto loadKV = [&](int j, int s) {
        uint32_t kb = kvbase + s * (2 * AKVSTG);
        uint32_t vb = kb + AKVSTG;
        const __half* ks = kbase + (size_t)(j * AK) * HD_;
        const __half* vs = vbase + (size_t)(j * AK) * HD_;
#pragma unroll
        for (int i = 0; i < 8; i++) {
            int idx = tid + i * 128;
            int row = idx >> 4, ch = idx & 15;
            int sc = ((ch & 7) ^ (row & 7)) | (ch & 8);
            cp16(kb + row * 256 + sc * 16, ks + (size_t)row * HD_ + ch * 8);
            cp16(vb + row * 256 + sc * 16, vs + (size_t)row * HD_ + ch * 8);
        }
    };

    loadKV(ord(0), 0); CP_COMMIT();

    for (int it = 0; it <= jmax; it++) {
        const int j  = ord(it);
        const int s0 = j * AK;
        __syncthreads();
        if (it + 1 <= jmax) { loadKV(ord(it + 1), (it + 1) & 1); CP_COMMIT(); CP_WAIT1(); }
        else                { CP_WAIT0(); }
        __syncthreads();

        uint32_t Kb = kvbase + (it & 1) * (2 * AKVSTG);
        uint32_t Vb = Kb + AKVSTG;

        float sacc[8][4];
#pragma unroll
        for (int nt = 0; nt < 8; nt++)
#pragma unroll
            for (int q = 0; q < 4; q++) sacc[nt][q] = 0.f;

#pragma unroll
        for (int kk = 0; kk < 8; kk++) {
#pragma unroll
            for (int ntp = 0; ntp < 4; ntp++) {
                int row = ntp * 16 + ((lane >> 4) << 3) + (lane & 7);
                int ch  = 2 * kk + ((lane >> 3) & 1);
                int sc  = ((ch & 7) ^ (row & 7)) | (ch & 8);
                uint32_t r0, r1, r2, r3;
                ldsm_x4(r0, r1, r2, r3, Kb + row * 256 + sc * 16);
                mma_16816(sacc[2*ntp],   qa[kk], r0, r1);
                mma_16816(sacc[2*ntp+1], qa[kk], r2, r3);
            }
        }

        float mtile[2] = {-1e30f, -1e30f};
        if (it == 0) {
            const int tg0 = t0 + wid * 16 + (lane >> 2);
#pragma unroll
            for (int nt = 0; nt < 8; nt++) {
                int sg = s0 + nt * 8 + ((lane & 3) << 1);
#pragma unroll
                for (int q = 0; q < 4; q++) {
                    int rsel = q >> 1;
                    int scol = sg + (q & 1);
                    int tg   = tg0 + (rsel ? 8 : 0);
                    float vv = sacc[nt][q] * scale;
                    if (scol > tg) vv = -1e30f;
                    sacc[nt][q] = vv;
                    mtile[rsel] = fmaxf(mtile[rsel], vv);
                }
            }
        } else {
#pragma unroll
            for (int nt = 0; nt < 8; nt++) {
#pragma unroll
                for (int q = 0; q < 4; q++) {
                    float vv = sacc[nt][q] * scale;
                    sacc[nt][q] = vv;
                    mtile[q >> 1] = fmaxf(mtile[q >> 1], vv);
                }
            }
        }
#pragma unroll
        for (int o2 = 1; o2 < 4; o2 <<= 1) {
            mtile[0] = fmaxf(mtile[0], __shfl_xor_sync(~0u, mtile[0], o2));
            mtile[1] = fmaxf(mtile[1], __shfl_xor_sync(~0u, mtile[1], o2));
        }
        float mnew[2] = {fmaxf(m_run[0], mtile[0]), fmaxf(m_run[1], mtile[1])};
        float corr[2] = {__expf(m_run[0] - mnew[0]), __expf(m_run[1] - mnew[1])};

        float pl[2] = {0.f, 0.f};
        uint32_t pa[4][4];
#pragma unroll
        for (int nt = 0; nt < 8; nt++) {
            float p0 = __expf(sacc[nt][0] - mnew[0]);
            float p1 = __expf(sacc[nt][1] - mnew[0]);
            float p2 = __expf(sacc[nt][2] - mnew[1]);
            float p3 = __expf(sacc[nt][3] - mnew[1]);
            pl[0] += p0 + p1; pl[1] += p2 + p3;
            int kk2 = nt >> 1, hi = nt & 1;
            pa[kk2][2*hi]     = packh2(p0, p1);
            pa[kk2][2*hi + 1] = packh2(p2, p3);
        }
#pragma unroll
        for (int o2 = 1; o2 < 4; o2 <<= 1) {
            pl[0] += __shfl_xor_sync(~0u, pl[0], o2);
            pl[1] += __shfl_xor_sync(~0u, pl[1], o2);
        }
        l_run[0] = l_run[0] * corr[0] + pl[0];
        l_run[1] = l_run[1] * corr[1] + pl[1];
        m_run[0] = mnew[0]; m_run[1] = mnew[1];

        bool need = !__all_sync(~0u, (corr[0] == 1.f) && (corr[1] == 1.f));
        if (need) {
#pragma unroll
            for (int nt = 0; nt < 16; nt++) {
                o[nt][0] *= corr[0]; o[nt][1] *= corr[0];
                o[nt][2] *= corr[1]; o[nt][3] *= corr[1];
            }
        }
#pragma unroll
        for (int kk2 = 0; kk2 < 4; kk2++) {
#pragma unroll
            for (int etp = 0; etp < 8; etp++) {
                int row = kk2 * 16 + ((lane >> 3) & 1) * 8 + (lane & 7);
                int ch  = etp * 2 + (lane >> 4);
                int sc  = ((ch & 7) ^ (row & 7)) | (ch & 8);
                uint32_t r0, r1, r2, r3;
                ldsm_x4_t(r0, r1, r2, r3, Vb + row * 256 + sc * 16);
                mma_16816(o[2*etp],   pa[kk2], r0, r1);
                mma_16816(o[2*etp+1], pa[kk2], r2, r3);
            }
        }
    }

    float inv0 = 1.f / l_run[0], inv1 = 1.f / l_run[1];
    const int tg = t0 + wid * 16 + (lane >> 2);
    size_t base0 = ((size_t)b * T_ + tg)     * D_ + h * HD_;
    size_t base1 = ((size_t)b * T_ + tg + 8) * D_ + h * HD_;
#pragma unroll
    for (int nt = 0; nt < 16; nt++) {
        int e = nt * 8 + ((lane & 3) << 1);
        *(__half2*)(g_att + base0 + e) = __floats2half2_rn(o[nt][0] * inv0, o[nt][1] * inv0);
        *(__half2*)(g_att + base1 + e) = __floats2half2_rn(o[nt][2] * inv1, o[nt][3] * inv1);
    }
}

// ------------------------------------------------------------------
// Launch: side stream hides weight conversion; head-grouped QKV GEMMs
// overlap with per-group attention on a second stream.
// ------------------------------------------------------------------
extern "C" void kernel_launch(void* const* d_in, const int* in_sizes, int n_in,
                              void* d_out, int out_size) {
    const float* x   = (const float*)d_in[0];
    const float* Wq  = (const float*)d_in[1];
    const float* bq  = (const float*)d_in[2];
    const float* Wk  = (const float*)d_in[3];
    const float* bk  = (const float*)d_in[4];
    const float* Wv  = (const float*)d_in[5];
    const float* bv  = (const float*)d_in[6];
    const float* W1  = (const float*)d_in[7];
    const float* b1  = (const float*)d_in[8];
    const float* W2  = (const float*)d_in[9];
    const float* b2  = (const float*)d_in[10];
    const float* g1  = (const float*)d_in[11];
    const float* be1 = (const float*)d_in[12];
    const float* g2  = (const float*)d_in[13];
    const float* be2 = (const float*)d_in[14];
    float* out = (float*)d_out;

    __half *pWq, *pWk, *pWv, *pW1, *pW2, *pH, *pH2;
    cudaGetSymbolAddress((void**)&pWq, g_Wq);
    cudaGetSymbolAddress((void**)&pWk, g_Wk);
    cudaGetSymbolAddress((void**)&pWv, g_Wv);
    cudaGetSymbolAddress((void**)&pW1, g_W1);
    cudaGetSymbolAddress((void**)&pW2, g_W2);
    cudaGetSymbolAddress((void**)&pH,  g_h);
    cudaGetSymbolAddress((void**)&pH2, g_h2);

    cudaFuncSetAttribute(gemm_kernel, cudaFuncAttributeMaxDynamicSharedMemorySize, GSMEM);
    cudaFuncSetAttribute(attn_kernel, cudaFuncAttributeMaxDynamicSharedMemorySize, ASMEM);

    static cudaStream_t s_side = nullptr, s_attn = nullptr;
    static cudaEvent_t ev_fork = nullptr, ev_qkvw = nullptr, ev_ffw = nullptr;
    static cudaEvent_t ev_g[4] = {nullptr, nullptr, nullptr, nullptr};
    static cudaEvent_t ev_alast = nullptr;
    if (s_side == nullptr) {
        cudaStreamCreateWithFlags(&s_side, cudaStreamNonBlocking);
        cudaStreamCreateWithFlags(&s_attn, cudaStreamNonBlocking);
        cudaEventCreateWithFlags(&ev_fork, cudaEventDisableTiming);
        cudaEventCreateWithFlags(&ev_qkvw, cudaEventDisableTiming);
        cudaEventCreateWithFlags(&ev_ffw,  cudaEventDisableTiming);
        for (int g = 0; g < 4; g++) cudaEventCreateWithFlags(&ev_g[g], cudaEventDisableTiming);
        cudaEventCreateWithFlags(&ev_alast, cudaEventDisableTiming);
    }

    const long nv8_qkv = (long)H_*D_*HD_/8;     // 524288
    const long nv8_ff  = (long)D_*DFF_/8;       // 2097152

    // Fork weight-conversion stream
    cudaEventRecord(ev_fork, 0);
    cudaStreamWaitEvent(s_side, ev_fork, 0);
    f2h3_kernel<<<(unsigned)(3*nv8_qkv/256), 256, 0, s_side>>>(
        (const float4*)Wq, (uint4*)pWq, nv8_qkv,
        (const float4*)Wk, (uint4*)pWk, nv8_qkv,
        (const float4*)Wv, (uint4*)pWv);
    cudaEventRecord(ev_qkvw, s_side);
    f2h3_kernel<<<(unsigned)(2*nv8_ff/256), 256, 0, s_side>>>(
        (const float4*)W1, (uint4*)pW1, nv8_ff,
        (const float4*)W2, (uint4*)pW2, nv8_ff,
        (const float4*)W2, (uint4*)pW2);
    cudaEventRecord(ev_ffw, s_side);

    // Main: LN1 (overlaps weight conversion)
    ln_kernel<<<R_, 256>>>(x, g1, be1, pH);

    // Head-grouped QKV GEMMs; attention per group on s_attn
    cudaStreamWaitEvent(0, ev_qkvw, 0);
    for (int g = 0; g < 4; g++) {
        gemm_kernel<<<dim3(12, R_ / BM), 256, GSMEM>>>(0, g, bq, bk, bv, b1, b2, out);
        cudaEventRecord(ev_g[g], 0);
        cudaStreamWaitEvent(s_attn, ev_g[g], 0);
        attn_kernel<<<dim3(T_ / AQ, B_ * 4), 128, ASMEM, s_attn>>>(g);
    }
    cudaEventRecord(ev_alast, s_attn);

    // Join: residual + LN2 needs all attention groups
    cudaStreamWaitEvent(0, ev_alast, 0);
    resid_ln_kernel<<<R_, 256>>>(x, g2, be2, out, pH2);

    cudaStreamWaitEvent(0, ev_ffw, 0);
    gemm_kernel<<<dim3(DFF_ / BN, R_ / BM), 256, GSMEM>>>(1, 0, bq, bk, bv, b1, b2, out);

    gemm_kernel<<<dim3(D_ / BN, R_ / BM), 256, GSMEM>>>(2, 0, bq, bk, bv, b1, b2, out);
}

// round 14
// speedup vs baseline: 1.0432x; 1.0432x over previous
#include <cuda_runtime.h>
#include <cuda_fp16.h>
#include <cstdint>

// Problem constants
#define B_   4
#define T_   2048
#define D_   2048
#define H_   16
#define HD_  128
#define DFF_ 8192
#define R_   (B_*T_)      // 8192 rows

// ------------------------------------------------------------------
// Device scratch
// ------------------------------------------------------------------
__device__ __align__(256) __half g_h  [(size_t)R_*D_];
__device__ __align__(256) __half g_h2 [(size_t)R_*D_];
__device__ __align__(256) __half g_Wq [(size_t)H_*D_*HD_];
__device__ __align__(256) __half g_Wk [(size_t)H_*D_*HD_];
__device__ __align__(256) __half g_Wv [(size_t)H_*D_*HD_];
__device__ __align__(256) __half g_W1 [(size_t)D_*DFF_];
__device__ __align__(256) __half g_W2 [(size_t)DFF_*D_];
__device__ __align__(256) __half g_q  [(size_t)B_*H_*T_*HD_];
__device__ __align__(256) __half g_k  [(size_t)B_*H_*T_*HD_];
__device__ __align__(256) __half g_v  [(size_t)B_*H_*T_*HD_];
__device__ __align__(256) __half g_att[(size_t)R_*D_];
__device__ __align__(256) __half g_ff [(size_t)R_*DFF_];

// ------------------------------------------------------------------
// Helpers
// ------------------------------------------------------------------
__device__ __forceinline__ uint32_t smem_u32(const void* p) {
    return (uint32_t)__cvta_generic_to_shared(p);
}
__device__ __forceinline__ void cp16(uint32_t dst, const void* src) {
    asm volatile("cp.async.cg.shared.global [%0], [%1], 16;" :: "r"(dst), "l"(src));
}
#define CP_COMMIT() asm volatile("cp.async.commit_group;")
#define CP_WAIT0()  asm volatile("cp.async.wait_group 0;")
#define CP_WAIT1()  asm volatile("cp.async.wait_group 1;")

__device__ __forceinline__ void ldsm_x4(uint32_t& r0, uint32_t& r1, uint32_t& r2, uint32_t& r3, uint32_t a) {
    asm volatile("ldmatrix.sync.aligned.m8n8.x4.shared.b16 {%0,%1,%2,%3}, [%4];"
                 : "=r"(r0), "=r"(r1), "=r"(r2), "=r"(r3) : "r"(a));
}
__device__ __forceinline__ void ldsm_x4_t(uint32_t& r0, uint32_t& r1, uint32_t& r2, uint32_t& r3, uint32_t a) {
    asm volatile("ldmatrix.sync.aligned.m8n8.x4.trans.shared.b16 {%0,%1,%2,%3}, [%4];"
                 : "=r"(r0), "=r"(r1), "=r"(r2), "=r"(r3) : "r"(a));
}
__device__ __forceinline__ void mma_16816(float* c, const uint32_t* a, uint32_t b0, uint32_t b1v) {
    asm volatile(
        "mma.sync.aligned.m16n8k16.row.col.f32.f16.f16.f32 "
        "{%0,%1,%2,%3}, {%4,%5,%6,%7}, {%8,%9}, {%0,%1,%2,%3};\n"
        : "+f"(c[0]), "+f"(c[1]), "+f"(c[2]), "+f"(c[3])
        : "r"(a[0]), "r"(a[1]), "r"(a[2]), "r"(a[3]), "r"(b0), "r"(b1v));
}
__device__ __forceinline__ uint32_t packh2(float a, float b) {
    __half2 h = __floats2half2_rn(a, b);
    return *reinterpret_cast<uint32_t*>(&h);
}

// ------------------------------------------------------------------
// fp32 -> fp16, 8 elems/thread, up to 3 concatenated ranges
// ------------------------------------------------------------------
__global__ void __launch_bounds__(256) f2h3_kernel(
    const float4* __restrict__ s0, uint4* __restrict__ d0, long n0,
    const float4* __restrict__ s1, uint4* __restrict__ d1, long n1,
    const float4* __restrict__ s2, uint4* __restrict__ d2)
{
    long i = (long)blockIdx.x * 256 + threadIdx.x;
    const float4* src; uint4* dst;
    if      (i < n0)       { src = s0; dst = d0; }
    else if (i < n0 + n1)  { src = s1; dst = d1; i -= n0; }
    else                   { src = s2; dst = d2; i -= n0 + n1; }
    float4 a = src[2*i], c = src[2*i + 1];
    __half2 h0 = __floats2half2_rn(a.x, a.y);
    __half2 h1 = __floats2half2_rn(a.z, a.w);
    __half2 h2 = __floats2half2_rn(c.x, c.y);
    __half2 h3 = __floats2half2_rn(c.z, c.w);
    uint4 o;
    o.x = *(uint32_t*)&h0; o.y = *(uint32_t*)&h1;
    o.z = *(uint32_t*)&h2; o.w = *(uint32_t*)&h3;
    dst[i] = o;
}

// ------------------------------------------------------------------
// LayerNorm (block per row of D_=2048, 256 threads) — vectorized 16B
// ------------------------------------------------------------------
__global__ void __launch_bounds__(256) ln_kernel(
    const float* __restrict__ x, const float* __restrict__ g,
    const float* __restrict__ b, __half* __restrict__ out)
{
    int r = blockIdx.x;
    size_t off = (size_t)r * D_;
    int c0 = threadIdx.x * 8;
    float4 xa = *(const float4*)(x + off + c0);
    float4 xb = *(const float4*)(x + off + c0 + 4);
    float v[8] = {xa.x, xa.y, xa.z, xa.w, xb.x, xb.y, xb.z, xb.w};
    float s = 0.f, s2 = 0.f;
#pragma unroll
    for (int j = 0; j < 8; j++) { s += v[j]; s2 += v[j]*v[j]; }
    __shared__ float red[32];
#pragma unroll
    for (int o = 16; o; o >>= 1) { s += __shfl_xor_sync(~0u, s, o); s2 += __shfl_xor_sync(~0u, s2, o); }
    int wid = threadIdx.x >> 5;
    if ((threadIdx.x & 31) == 0) { red[wid] = s; red[8 + wid] = s2; }
    __syncthreads();
    if (threadIdx.x < 32) {
        float a  = (threadIdx.x < 8) ? red[threadIdx.x]   : 0.f;
        float c2 = (threadIdx.x < 8) ? red[8+threadIdx.x] : 0.f;
#pragma unroll
        for (int o = 4; o; o >>= 1) { a += __shfl_xor_sync(~0u, a, o); c2 += __shfl_xor_sync(~0u, c2, o); }
        if (threadIdx.x == 0) { red[16] = a; red[17] = c2; }
    }
    __syncthreads();
    float mu  = red[16] * (1.f / D_);
    float var = red[17] * (1.f / D_) - mu * mu;
    float rs  = rsqrtf(var + 1e-5f);
    float4 ga = *(const float4*)(g + c0), gb = *(const float4*)(g + c0 + 4);
    float4 ba = *(const float4*)(b + c0), bb = *(const float4*)(b + c0 + 4);
    float gg[8]  = {ga.x, ga.y, ga.z, ga.w, gb.x, gb.y, gb.z, gb.w};
    float bbv[8] = {ba.x, ba.y, ba.z, ba.w, bb.x, bb.y, bb.z, bb.w};
    uint4 o4;
    uint32_t* op = (uint32_t*)&o4;
#pragma unroll
    for (int j = 0; j < 4; j++) {
        op[j] = packh2((v[2*j]   - mu) * rs * gg[2*j]   + bbv[2*j],
                       (v[2*j+1] - mu) * rs * gg[2*j+1] + bbv[2*j+1]);
    }
    *(uint4*)(out + off + c0) = o4;
}

// Fused: x1 = x + att ; write x1 (fp32) ; h2 = LN(x1) — vectorized 16B
__global__ void __launch_bounds__(256) resid_ln_kernel(
    const float* __restrict__ x, const float* __restrict__ g,
    const float* __restrict__ b, float* __restrict__ xout,
    __half* __restrict__ h2)
{
    int r = blockIdx.x;
    size_t off = (size_t)r * D_;
    int c0 = threadIdx.x * 8;
    float4 xa = *(const float4*)(x + off + c0);
    float4 xb = *(const float4*)(x + off + c0 + 4);
    uint4 at = *(const uint4*)(g_att + off + c0);
    const __half2* ah = (const __half2*)&at;
    float v[8];
    {
        float2 a0 = __half22float2(ah[0]), a1 = __half22float2(ah[1]);
        float2 a2 = __half22float2(ah[2]), a3 = __half22float2(ah[3]);
        v[0] = xa.x + a0.x; v[1] = xa.y + a0.y;
        v[2] = xa.z + a1.x; v[3] = xa.w + a1.y;
        v[4] = xb.x + a2.x; v[5] = xb.y + a2.y;
        v[6] = xb.z + a3.x; v[7] = xb.w + a3.y;
    }
    *(float4*)(xout + off + c0)     = make_float4(v[0], v[1], v[2], v[3]);
    *(float4*)(xout + off + c0 + 4) = make_float4(v[4], v[5], v[6], v[7]);
    float s = 0.f, s2 = 0.f;
#pragma unroll
    for (int j = 0; j < 8; j++) { s += v[j]; s2 += v[j]*v[j]; }
    __shared__ float red[32];
#pragma unroll
    for (int o = 16; o; o >>= 1) { s += __shfl_xor_sync(~0u, s, o); s2 += __shfl_xor_sync(~0u, s2, o); }
    int wid = threadIdx.x >> 5;
    if ((threadIdx.x & 31) == 0) { red[wid] = s; red[8 + wid] = s2; }
    __syncthreads();
    if (threadIdx.x < 32) {
        float a  = (threadIdx.x < 8) ? red[threadIdx.x]   : 0.f;
        float c2 = (threadIdx.x < 8) ? red[8+threadIdx.x] : 0.f;
#pragma unroll
        for (int o = 4; o; o >>= 1) { a += __shfl_xor_sync(~0u, a, o); c2 += __shfl_xor_sync(~0u, c2, o); }
        if (threadIdx.x == 0) { red[16] = a; red[17] = c2; }
    }
    __syncthreads();
    float mu  = red[16] * (1.f / D_);
    float var = red[17] * (1.f / D_) - mu * mu;
    float rs  = rsqrtf(var + 1e-5f);
    float4 ga = *(const float4*)(g + c0), gb = *(const float4*)(g + c0 + 4);
    float4 ba = *(const float4*)(b + c0), bb = *(const float4*)(b + c0 + 4);
    float gg[8]  = {ga.x, ga.y, ga.z, ga.w, gb.x, gb.y, gb.z, gb.w};
    float bbv[8] = {ba.x, ba.y, ba.z, ba.w, bb.x, bb.y, bb.z, bb.w};
    uint4 o4;
    uint32_t* op = (uint32_t*)&o4;
#pragma unroll
    for (int j = 0; j < 4; j++) {
        op[j] = packh2((v[2*j]   - mu) * rs * gg[2*j]   + bbv[2*j],
                       (v[2*j+1] - mu) * rs * gg[2*j+1] + bbv[2*j+1]);
    }
    *(uint4*)(h2 + off + c0) = o4;
}

// ------------------------------------------------------------------
// GEMM: C[M,N] = A[M,K]*B[K,N], 3-stage cp.async, ldmatrix, swizzled.
// BM=128, BN=128, BK=64; 256 threads (2x4 warps), warp tile 64x32.
// 2 CTAs/SM, one __syncthreads per k-tile. Monolithic QKV (mode 0).
// ------------------------------------------------------------------
#define BM 128
#define BN 128
#define BK 64
#define ASTG (BM*BK*2)            // 16384 B
#define BSTG (BK*BN*2)            // 16384 B
#define STG  (ASTG + BSTG)        // 32768 B
#define GSMEM (3*STG)             // 98304 B

__global__ void __launch_bounds__(256, 2) gemm_kernel(
    int mode,
    const float* __restrict__ bq, const float* __restrict__ bk, const float* __restrict__ bv,
    const float* __restrict__ b1, const float* __restrict__ b2,
    float* __restrict__ xout)
{
    const __half* A; int K;
    if (mode == 0)      { A = g_h;  K = D_;   }
    else if (mode == 1) { A = g_h2; K = D_;   }
    else                { A = g_ff; K = DFF_; }

    const int m0 = blockIdx.y * BM;
    const int n0 = blockIdx.x * BN;
    const int nkt = K / BK;

    extern __shared__ __half dsm[];
    const uint32_t sbase = smem_u32(dsm);

    const int tid  = threadIdx.x;
    const int wid  = tid >> 5;
    const int lane = tid & 31;
    const int wm   = wid & 1;
    const int wn   = wid >> 1;

    float acc[4][4][4];
#pragma unroll
    for (int i = 0; i < 4; i++)
#pragma unroll
        for (int j = 0; j < 4; j++)
#pragma unroll
            for (int q = 0; q < 4; q++) acc[i][j][q] = 0.f;

    auto loadStage = [&](int kt, int s) {
        uint32_t sA = sbase + s * STG;
        uint32_t sB = sA + ASTG;
#pragma unroll
        for (int i = 0; i < 4; i++) {
            int idx = tid + i * 256;
            int r = idx >> 3, c = idx & 7;
            int sc = c ^ (r & 7);
            cp16(sA + r * 128 + sc * 16, A + (size_t)(m0 + r) * K + kt * BK + c * 8);
        }
#pragma unroll
        for (int i = 0; i < 4; i++) {
            int idx = tid + i * 256;
            int r = idx >> 4, c = idx & 15;
            int sc = ((c & 7) ^ (r & 7)) | (c & 8);
            int n = n0 + c * 8;
            const __half* src;
            if (mode == 0) {
                int which = n >> 11, head = (n >> 7) & 15, e = n & 127;
                const __half* W = (which == 0) ? g_Wq : (which == 1) ? g_Wk : g_Wv;
                src = W + (size_t)head * (D_ * HD_) + (size_t)(kt * BK + r) * HD_ + e;
            } else if (mode == 1) {
                src = g_W1 + (size_t)(kt * BK + r) * DFF_ + n;
            } else {
                src = g_W2 + (size_t)(kt * BK + r) * D_ + n;
            }
            cp16(sB + r * 256 + sc * 16, src);
        }
    };

    loadStage(0, 0); CP_COMMIT();
    loadStage(1, 1); CP_COMMIT();

    for (int kt = 0; kt < nkt; kt++) {
        if (kt + 1 < nkt) { CP_WAIT1(); } else { CP_WAIT0(); }
        __syncthreads();
        if (kt + 2 < nkt) { loadStage(kt + 2, (kt + 2) % 3); CP_COMMIT(); }

        uint32_t sA = sbase + (kt % 3) * STG;
        uint32_t sB = sA + ASTG;

#pragma unroll
        for (int kk = 0; kk < 4; kk++) {
            uint32_t a[4][4];
#pragma unroll
            for (int mt = 0; mt < 4; mt++) {
                int row = wm * 64 + mt * 16 + (lane & 15);
                int ch  = 2 * kk + (lane >> 4);
                ldsm_x4(a[mt][0], a[mt][1], a[mt][2], a[mt][3],
                        sA + row * 128 + ((ch ^ (row & 7)) << 4));
            }
            uint32_t bf[4][2];
#pragma unroll
            for (int ntp = 0; ntp < 2; ntp++) {
                int row = kk * 16 + ((lane >> 3) & 1) * 8 + (lane & 7);
                int ch  = wn * 4 + ntp * 2 + (lane >> 4);
                int sc  = ((ch & 7) ^ (row & 7)) | (ch & 8);
                ldsm_x4_t(bf[2*ntp][0], bf[2*ntp][1], bf[2*ntp+1][0], bf[2*ntp+1][1],
                          sB + row * 256 + sc * 16);
            }
#pragma unroll
            for (int nt = 0; nt < 4; nt++)
#pragma unroll
                for (int mt = 0; mt < 4; mt++)
                    mma_16816(acc[mt][nt], a[mt], bf[nt][0], bf[nt][1]);
        }
    }

    // ---- Epilogue ----
    if (mode == 0) {
        int which = n0 >> 11, head = (n0 >> 7) & 15;
        const float* bias = ((which == 0) ? bq : (which == 1) ? bk : bv) + head * HD_;
        __half* qkv = (which == 0) ? g_q : (which == 1) ? g_k : g_v;
#pragma unroll
        for (int mt = 0; mt < 4; mt++) {
#pragma unroll
            for (int nt = 0; nt < 4; nt++) {
                float* cc = acc[mt][nt];
                int row0 = m0 + wm * 64 + mt * 16 + (lane >> 2);
                int e    = wn * 32 + nt * 8 + ((lane & 3) << 1);
                float bb0 = bias[e], bb1 = bias[e + 1];
#pragma unroll
                for (int rr = 0; rr < 2; rr++) {
                    int row = row0 + rr * 8;
                    int bb = row >> 11, t = row & (T_ - 1);
                    __half* dst = qkv + (((size_t)(bb * H_ + head) * T_ + t) * HD_) + e;
                    *(__half2*)dst = __floats2half2_rn(cc[rr*2] + bb0, cc[rr*2+1] + bb1);
                }
            }
        }
    } else if (mode == 1) {
#pragma unroll
        for (int mt = 0; mt < 4; mt++) {
#pragma unroll
            for (int nt = 0; nt < 4; nt++) {
                float* cc = acc[mt][nt];
                int row0 = m0 + wm * 64 + mt * 16 + (lane >> 2);
                int col  = n0 + wn * 32 + nt * 8 + ((lane & 3) << 1);
                float bb0 = b1[col], bb1 = b1[col + 1];
#pragma unroll
                for (int rr = 0; rr < 2; rr++) {
                    int row = row0 + rr * 8;
                    float v0 = fmaxf(cc[rr*2]   + bb0, 0.f);
                    float v1 = fmaxf(cc[rr*2+1] + bb1, 0.f);
                    *(__half2*)(g_ff + (size_t)row * DFF_ + col) = __floats2half2_rn(v0, v1);
                }
            }
        }
    } else {
#pragma unroll
        for (int mt = 0; mt < 4; mt++) {
#pragma unroll
            for (int nt = 0; nt < 4; nt++) {
                float* cc = acc[mt][nt];
                int row0 = m0 + wm * 64 + mt * 16 + (lane >> 2);
                int col  = n0 + wn * 32 + nt * 8 + ((lane & 3) << 1);
                float bb0 = b2[col], bb1 = b2[col + 1];
#pragma unroll
                for (int rr = 0; rr < 2; rr++) {
                    int row = row0 + rr * 8;
                    float2* d = (float2*)(xout + (size_t)row * D_ + col);
                    float2 val = *d;
                    val.x += cc[rr*2]   + bb0;
                    val.y += cc[rr*2+1] + bb1;
                    *d = val;
                }
            }
        }
    }
}

// ------------------------------------------------------------------
// Flash attention: grid (T/64, B*H), 128 threads (4 warps x 16 q rows)
// Heavy-first (reversed) block order; diagonal tile first; double-
// buffered cp.async K/V; rescale skip.
// ------------------------------------------------------------------
#define AQ 64
#define AK 64
#define AKVSTG (AK*HD_*2)          // 16384 B per tensor per stage
#define ASMEM  (4*AKVSTG)          // 65536 B

__global__ void __launch_bounds__(128) attn_kernel() {
    const int bh = blockIdx.y;
    const int b  = bh >> 4, h = bh & 15;
    const int t0 = (gridDim.x - 1 - blockIdx.x) * AQ;   // heavy CTAs first

    const __half* qbase = g_q + (size_t)bh * T_ * HD_;
    const __half* kbase = g_k + (size_t)bh * T_ * HD_;
    const __half* vbase = g_v + (size_t)bh * T_ * HD_;

    extern __shared__ __half kvsm[];
    const uint32_t kvbase = smem_u32(kvsm);

    const int tid  = threadIdx.x;
    const int wid  = tid >> 5;
    const int lane = tid & 31;
    const int qr   = wid * 16 + (lane >> 2);

    uint32_t qa[8][4];
    {
        const __half* qp = qbase + (size_t)t0 * HD_;
#pragma unroll
        for (int kk = 0; kk < 8; kk++) {
            int c = ((lane & 3) << 1) + kk * 16;
            qa[kk][0] = *(const uint32_t*)(qp + (size_t)qr       * HD_ + c);
            qa[kk][1] = *(const uint32_t*)(qp + (size_t)(qr + 8) * HD_ + c);
            qa[kk][2] = *(const uint32_t*)(qp + (size_t)qr       * HD_ + c + 8);
            qa[kk][3] = *(const uint32_t*)(qp + (size_t)(qr + 8) * HD_ + c + 8);
        }
    }

    float m_run[2] = {-1e30f, -1e30f};
    float l_run[2] = {0.f, 0.f};
    float o[16][4];
#pragma unroll
    for (int i = 0; i < 16; i++)
#pragma unroll
        for (int q = 0; q < 4; q++) o[i][q] = 0.f;

    const float scale = 0.08838834764831845f;
    const int jmax = t0 / AK;

    auto ord = [&](int i) { return (i == 0) ? jmax : (i - 1); };

    auto loadKV = [&](int j, int s) {
        uint32_t kb = kvbase + s * (2 * AKVSTG);
        uint32_t vb = kb + AKVSTG;
        const __half* ks = kbase + (size_t)(j * AK) * HD_;
        const __half* vs = vbase + (size_t)(j * AK) * HD_;
#pragma unroll
        for (int i = 0; i < 8; i++) {
            int idx = tid + i * 128;
            int row = idx >> 4, ch = idx & 15;
            int sc = ((ch & 7) ^ (row & 7)) | (ch & 8);
            cp16(kb + row * 256 + sc * 16, ks + (size_t)row * HD_ + ch * 8);
            cp16(vb + row * 256 + sc * 16, vs + (size_t)row * HD_ + ch * 8);
        }
    };

    loadKV(ord(0), 0); CP_COMMIT();

    for (int it = 0; it <= jmax; it++) {
        const int j  = ord(it);
        const int s0 = j * AK;
        __syncthreads();
        if (it + 1 <= jmax) { loadKV(ord(it + 1), (it + 1) & 1); CP_COMMIT(); CP_WAIT1(); }
        else                { CP_WAIT0(); }
        __syncthreads();

        uint32_t Kb = kvbase + (it & 1) * (2 * AKVSTG);
        uint32_t Vb = Kb + AKVSTG;

        float sacc[8][4];
#pragma unroll
        for (int nt = 0; nt < 8; nt++)
#pragma unroll
            for (int q = 0; q < 4; q++) sacc[nt][q] = 0.f;

#pragma unroll
        for (int kk = 0; kk < 8; kk++) {
#pragma unroll
            for (int ntp = 0; ntp < 4; ntp++) {
                int row = ntp * 16 + ((lane >> 4) << 3) + (lane & 7);
                int ch  = 2 * kk + ((lane >> 3) & 1);
                int sc  = ((ch & 7) ^ (row & 7)) | (ch & 8);
                uint32_t r0, r1, r2, r3;
                ldsm_x4(r0, r1, r2, r3, Kb + row * 256 + sc * 16);
                mma_16816(sacc[2*ntp],   qa[kk], r0, r1);
                mma_16816(sacc[2*ntp+1], qa[kk], r2, r3);
            }
        }

        float mtile[2] = {-1e30f, -1e30f};
        if (it == 0) {
            const int tg0 = t0 + wid * 16 + (lane >> 2);
#pragma unroll
            for (int nt = 0; nt < 8; nt++) {
                int sg = s0 + nt * 8 + ((lane & 3) << 1);
#pragma unroll
                for (int q = 0; q < 4; q++) {
                    int rsel = q >> 1;
                    int scol = sg + (q & 1);
                    int tg   = tg0 + (rsel ? 8 : 0);
                    float vv = sacc[nt][q] * scale;
                    if (scol > tg) vv = -1e30f;
                    sacc[nt][q] = vv;
                    mtile[rsel] = fmaxf(mtile[rsel], vv);
                }
            }
        } else {
#pragma unroll
            for (int nt = 0; nt < 8; nt++) {
#pragma unroll
                for (int q = 0; q < 4; q++) {
                    float vv = sacc[nt][q] * scale;
                    sacc[nt][q] = vv;
                    mtile[q >> 1] = fmaxf(mtile[q >> 1], vv);
                }
            }
        }
#pragma unroll
        for (int o2 = 1; o2 < 4; o2 <<= 1) {
            mtile[0] = fmaxf(mtile[0], __shfl_xor_sync(~0u, mtile[0], o2));
            mtile[1] = fmaxf(mtile[1], __shfl_xor_sync(~0u, mtile[1], o2));
        }
        float mnew[2] = {fmaxf(m_run[0], mtile[0]), fmaxf(m_run[1], mtile[1])};
        float corr[2] = {__expf(m_run[0] - mnew[0]), __expf(m_run[1] - mnew[1])};

        float pl[2] = {0.f, 0.f};
        uint32_t pa[4][4];
#pragma unroll
        for (int nt = 0; nt < 8; nt++) {
            float p0 = __expf(sacc[nt][0] - mnew[0]);
            float p1 = __expf(sacc[nt][1] - mnew[0]);
            float p2 = __expf(sacc[nt][2] - mnew[1]);
            float p3 = __expf(sacc[nt][3] - mnew[1]);
            pl[0] += p0 + p1; pl[1] += p2 + p3;
            int kk2 = nt >> 1, hi = nt & 1;
            pa[kk2][2*hi]     = packh2(p0, p1);
            pa[kk2][2*hi + 1] = packh2(p2, p3);
        }
#pragma unroll
        for (int o2 = 1; o2 < 4; o2 <<= 1) {
            pl[0] += __shfl_xor_sync(~0u, pl[0], o2);
            pl[1] += __shfl_xor_sync(~0u, pl[1], o2);
        }
        l_run[0] = l_run[0] * corr[0] + pl[0];
        l_run[1] = l_run[1] * corr[1] + pl[1];
        m_run[0] = mnew[0]; m_run[1] = mnew[1];

        bool need = !__all_sync(~0u, (corr[0] == 1.f) && (corr[1] == 1.f));
        if (need) {
#pragma unroll
            for (int nt = 0; nt < 16; nt++) {
                o[nt][0] *= corr[0]; o[nt][1] *= corr[0];
                o[nt][2] *= corr[1]; o[nt][3] *= corr[1];
            }
        }
#pragma unroll
        for (int kk2 = 0; kk2 < 4; kk2++) {
#pragma unroll
            for (int etp = 0; etp < 8; etp++) {
                int row = kk2 * 16 + ((lane >> 3) & 1) * 8 + (lane & 7);
                int ch  = etp * 2 + (lane >> 4);
                int sc  = ((ch & 7) ^ (row & 7)) | (ch & 8);
                uint32_t r0, r1, r2, r3;
                ldsm_x4_t(r0, r1, r2, r3, Vb + row * 256 + sc * 16);
                mma_16816(o[2*etp],   pa[kk2], r0, r1);
                mma_16816(o[2*etp+1], pa[kk2], r2, r3);
            }
        }
    }

    float inv0 = 1.f / l_run[0], inv1 = 1.f / l_run[1];
    const int tg = t0 + wid * 16 + (lane >> 2);
    size_t base0 = ((size_t)b * T_ + tg)     * D_ + h * HD_;
    size_t base1 = ((size_t)b * T_ + tg + 8) * D_ + h * HD_;
#pragma unroll
    for (int nt = 0; nt < 16; nt++) {
        int e = nt * 8 + ((lane & 3) << 1);
        *(__half2*)(g_att + base0 + e) = __floats2half2_rn(o[nt][0] * inv0, o[nt][1] * inv0);
        *(__half2*)(g_att + base1 + e) = __floats2half2_rn(o[nt][2] * inv1, o[nt][3] * inv1);
    }
}

// ------------------------------------------------------------------
// Launch: side stream hides weight conversion under LN1 / QKV GEMM.
// ------------------------------------------------------------------
extern "C" void kernel_launch(void* const* d_in, const int* in_sizes, int n_in,
                              void* d_out, int out_size) {
    const float* x   = (const float*)d_in[0];
    const float* Wq  = (const float*)d_in[1];
    const float* bq  = (const float*)d_in[2];
    const float* Wk  = (const float*)d_in[3];
    const float* bk  = (const float*)d_in[4];
    const float* Wv  = (const float*)d_in[5];
    const float* bv  = (const float*)d_in[6];
    const float* W1  = (const float*)d_in[7];
    const float* b1  = (const float*)d_in[8];
    const float* W2  = (const float*)d_in[9];
    const float* b2  = (const float*)d_in[10];
    const float* g1  = (const float*)d_in[11];
    const float* be1 = (const float*)d_in[12];
    const float* g2  = (const float*)d_in[13];
    const float* be2 = (const float*)d_in[14];
    float* out = (float*)d_out;

    __half *pWq, *pWk, *pWv, *pW1, *pW2, *pH, *pH2;
    cudaGetSymbolAddress((void**)&pWq, g_Wq);
    cudaGetSymbolAddress((void**)&pWk, g_Wk);
    cudaGetSymbolAddress((void**)&pWv, g_Wv);
    cudaGetSymbolAddress((void**)&pW1, g_W1);
    cudaGetSymbolAddress((void**)&pW2, g_W2);
    cudaGetSymbolAddress((void**)&pH,  g_h);
    cudaGetSymbolAddress((void**)&pH2, g_h2);

    cudaFuncSetAttribute(gemm_kernel, cudaFuncAttributeMaxDynamicSharedMemorySize, GSMEM);
    cudaFuncSetAttribute(attn_kernel, cudaFuncAttributeMaxDynamicSharedMemorySize, ASMEM);

    static cudaStream_t s_side = nullptr;
    static cudaEvent_t ev_fork = nullptr, ev_qkvw = nullptr, ev_ffw = nullptr;
    if (s_side == nullptr) {
        cudaStreamCreateWithFlags(&s_side, cudaStreamNonBlocking);
        cudaEventCreateWithFlags(&ev_fork, cudaEventDisableTiming);
        cudaEventCreateWithFlags(&ev_qkvw, cudaEventDisableTiming);
        cudaEventCreateWithFlags(&ev_ffw,  cudaEventDisableTiming);
    }

    const long nv8_qkv = (long)H_*D_*HD_/8;     // 524288
    const long nv8_ff  = (long)D_*DFF_/8;       // 2097152

    cudaEventRecord(ev_fork, 0);
    cudaStreamWaitEvent(s_side, ev_fork, 0);

    f2h3_kernel<<<(unsigned)(3*nv8_qkv/256), 256, 0, s_side>>>(
        (const float4*)Wq, (uint4*)pWq, nv8_qkv,
        (const float4*)Wk, (uint4*)pWk, nv8_qkv,
        (const float4*)Wv, (uint4*)pWv);
    cudaEventRecord(ev_qkvw, s_side);
    f2h3_kernel<<<(unsigned)(2*nv8_ff/256), 256, 0, s_side>>>(
        (const float4*)W1, (uint4*)pW1, nv8_ff,
        (const float4*)W2, (uint4*)pW2, nv8_ff,
        (const float4*)W2, (uint4*)pW2);
    cudaEventRecord(ev_ffw, s_side);

    ln_kernel<<<R_, 256>>>(x, g1, be1, pH);

    cudaStreamWaitEvent(0, ev_qkvw, 0);
    gemm_kernel<<<dim3(6144 / BN, R_ / BM), 256, GSMEM>>>(0, bq, bk, bv, b1, b2, out);

    attn_kernel<<<dim3(T_ / AQ, B_ * H_), 128, ASMEM>>>();

    resid_ln_kernel<<<R_, 256>>>(x, g2, be2, out, pH2);

    cudaStreamWaitEvent(0, ev_ffw, 0);
    gemm_kernel<<<dim3(DFF_ / BN, R_ / BM), 256, GSMEM>>>(1, bq, bk, bv, b1, b2, out);

    gemm_kernel<<<dim3(D_ / BN, R_ / BM), 256, GSMEM>>>(2, bq, bk, bv, b1, b2, out);
}